// round 1
// baseline (speedup 1.0000x reference)
#include <cuda_runtime.h>
#include <cstdint>

// Problem shape (fixed for this problem instance)
constexpr int M_ENS = 8;
constexpr int B_DIM = 4096;
constexpr int I_DIM = 2048;
constexpr int O_DIM = 2048;

// Scratch: sampled weights + bias (allowed: __device__ globals, no cudaMalloc)
__device__ float g_W[(size_t)M_ENS * I_DIM * O_DIM];   // 134 MB
__device__ float g_bias[M_ENS * O_DIM];

// ---------------------------------------------------------------------------
// Kernel 1: w = mu + softplus(rho) * eps    (vectorized, memory-bound)
// ---------------------------------------------------------------------------
__device__ __forceinline__ float softplus_f(float r) {
    // rho ~ -7 +/- ~0.6 here; guard anyway for stability
    return (r > 15.0f) ? r : log1pf(__expf(r));
}

__global__ void sample_w_kernel(const float* __restrict__ mu,
                                const float* __restrict__ rho,
                                const float* __restrict__ eps,
                                size_t n4) {
    const float4* mu4  = reinterpret_cast<const float4*>(mu);
    const float4* rho4 = reinterpret_cast<const float4*>(rho);
    const float4* eps4 = reinterpret_cast<const float4*>(eps);
    float4* out4 = reinterpret_cast<float4*>(g_W);
    size_t stride = (size_t)gridDim.x * blockDim.x;
    for (size_t i = (size_t)blockIdx.x * blockDim.x + threadIdx.x; i < n4; i += stride) {
        float4 m = mu4[i], r = rho4[i], e = eps4[i];
        float4 o;
        o.x = fmaf(softplus_f(r.x), e.x, m.x);
        o.y = fmaf(softplus_f(r.y), e.y, m.y);
        o.z = fmaf(softplus_f(r.z), e.z, m.z);
        o.w = fmaf(softplus_f(r.w), e.w, m.w);
        out4[i] = o;
    }
}

__global__ void sample_b_kernel(const float* __restrict__ mu,
                                const float* __restrict__ rho,
                                const float* __restrict__ eps,
                                int n) {
    int i = blockIdx.x * blockDim.x + threadIdx.x;
    if (i < n) {
        g_bias[i] = fmaf(softplus_f(rho[i]), eps[i], mu[i]);
    }
}

// ---------------------------------------------------------------------------
// Kernel 2: batched SGEMM  out[m] = x[m] @ W[m] + bias[m]
//   Block tile 128x128, K-tile 16, 256 threads, 8x8 per-thread microtile.
// ---------------------------------------------------------------------------
__global__ __launch_bounds__(256)
void sgemm_kernel(const float* __restrict__ X, float* __restrict__ Out) {
    const int m = blockIdx.z;
    const float* A  = X    + (size_t)m * B_DIM * I_DIM;
    const float* Bw = g_W  + (size_t)m * I_DIM * O_DIM;
    const float* bv = g_bias + m * O_DIM;
    float* C = Out + (size_t)m * B_DIM * O_DIM;

    const int row0 = blockIdx.y * 128;   // over B
    const int col0 = blockIdx.x * 128;   // over O

    __shared__ float As[16][128];   // transposed: As[k][row]
    __shared__ float Bs[16][128];   // Bs[k][col]

    const int tid = threadIdx.x;
    const int tr = (tid / 16) * 8;   // thread row base in tile
    const int tc = (tid % 16) * 8;   // thread col base in tile

    // load mapping
    const int aRow = tid >> 2;        // 0..63 (two passes cover 128 rows)
    const int aCol = (tid & 3) * 4;   // 0,4,8,12
    const int bRow = tid >> 5;        // 0..7  (two passes cover 16 rows)
    const int bCol = (tid & 31) * 4;  // 0..124

    float acc[8][8];
#pragma unroll
    for (int i = 0; i < 8; i++)
#pragma unroll
        for (int j = 0; j < 8; j++) acc[i][j] = 0.0f;

    for (int k0 = 0; k0 < I_DIM; k0 += 16) {
        // A tile: 128 rows x 16 k, stored transposed into As[k][row]
#pragma unroll
        for (int h = 0; h < 2; h++) {
            int r = aRow + h * 64;
            float4 v = *reinterpret_cast<const float4*>(
                A + (size_t)(row0 + r) * I_DIM + k0 + aCol);
            As[aCol + 0][r] = v.x;
            As[aCol + 1][r] = v.y;
            As[aCol + 2][r] = v.z;
            As[aCol + 3][r] = v.w;
        }
        // B tile: 16 k x 128 cols
#pragma unroll
        for (int h = 0; h < 2; h++) {
            int r = bRow + h * 8;
            float4 v = *reinterpret_cast<const float4*>(
                Bw + (size_t)(k0 + r) * O_DIM + col0 + bCol);
            *reinterpret_cast<float4*>(&Bs[r][bCol]) = v;
        }
        __syncthreads();

#pragma unroll
        for (int kk = 0; kk < 16; kk++) {
            float a[8], b[8];
#pragma unroll
            for (int i = 0; i < 8; i++) a[i] = As[kk][tr + i];
#pragma unroll
            for (int j = 0; j < 8; j++) b[j] = Bs[kk][tc + j];
#pragma unroll
            for (int i = 0; i < 8; i++)
#pragma unroll
                for (int j = 0; j < 8; j++)
                    acc[i][j] = fmaf(a[i], b[j], acc[i][j]);
        }
        __syncthreads();
    }

    // epilogue: add bias, vectorized stores
    float bias_reg[8];
#pragma unroll
    for (int j = 0; j < 8; j++) bias_reg[j] = __ldg(&bv[col0 + tc + j]);

#pragma unroll
    for (int i = 0; i < 8; i++) {
        float* crow = C + (size_t)(row0 + tr + i) * O_DIM + col0 + tc;
#pragma unroll
        for (int j = 0; j < 8; j += 4) {
            float4 v;
            v.x = acc[i][j + 0] + bias_reg[j + 0];
            v.y = acc[i][j + 1] + bias_reg[j + 1];
            v.z = acc[i][j + 2] + bias_reg[j + 2];
            v.w = acc[i][j + 3] + bias_reg[j + 3];
            *reinterpret_cast<float4*>(crow + j) = v;
        }
    }
}

// ---------------------------------------------------------------------------
// Launch: inputs (metadata order): x, weight_mu, weight_rho, bias_mu,
//         bias_rho, eps_w, eps_b
// ---------------------------------------------------------------------------
extern "C" void kernel_launch(void* const* d_in, const int* in_sizes, int n_in,
                              void* d_out, int out_size) {
    const float* x        = (const float*)d_in[0];
    const float* w_mu     = (const float*)d_in[1];
    const float* w_rho    = (const float*)d_in[2];
    const float* b_mu     = (const float*)d_in[3];
    const float* b_rho    = (const float*)d_in[4];
    const float* eps_w    = (const float*)d_in[5];
    const float* eps_b    = (const float*)d_in[6];
    float* out = (float*)d_out;

    // 1) sample weights into scratch
    size_t n_w4 = (size_t)M_ENS * I_DIM * O_DIM / 4;
    sample_w_kernel<<<4096, 256>>>(w_mu, w_rho, eps_w, n_w4);

    int n_b = M_ENS * O_DIM;
    sample_b_kernel<<<(n_b + 255) / 256, 256>>>(b_mu, b_rho, eps_b, n_b);

    // 2) batched SGEMM + bias
    dim3 grid(O_DIM / 128, B_DIM / 128, M_ENS);  // 16 x 32 x 8
    sgemm_kernel<<<grid, 256>>>(x, out);
}

// round 4
// speedup vs baseline: 2.9884x; 2.9884x over previous
#include <cuda_runtime.h>
#include <cstdint>

// ---------------------------------------------------------------------------
// Problem shape
// ---------------------------------------------------------------------------
constexpr int M_ENS = 8, B_DIM = 4096, I_DIM = 2048, O_DIM = 2048;

// GEMM tiling: CTA = 128 (batch rows) x 256 (out cols), K-tile 32.
constexpr int CT_M = 128, CT_N = 256, CT_K = 32;
constexpr int PAD = 36;                    // padded smem row length in floats
constexpr int A_ST = CT_M * PAD;           // 4608 floats
constexpr int B_ST = CT_N * PAD;           // 9216 floats
constexpr int STAGE_F = A_ST + B_ST;       // 13824 floats = 55296 B
constexpr int STAGES = 3;
constexpr int SMEM_BYTES = STAGES * STAGE_F * 4;   // 165888

// ---------------------------------------------------------------------------
// Scratch (device globals; no cudaMalloc allowed)
// Staged layouts keep global row-major [rows][2048 k], but within every
// 32-k group the order is permuted: k' = (k%4)*8 + k/4. This makes each
// thread's mma fragment elements contiguous (float4) in shared memory.
// ---------------------------------------------------------------------------
__device__ __align__(128) float g_Xs[(size_t)M_ENS * B_DIM * I_DIM];  // x, rounded+permuted
__device__ __align__(128) float g_Ws[(size_t)M_ENS * O_DIM * I_DIM];  // W^T, sampled+rounded+permuted
__device__ float g_bias[M_ENS * O_DIM];

// ---------------------------------------------------------------------------
// Helpers
// ---------------------------------------------------------------------------
__device__ __forceinline__ float tf32_rna(float x) {
    uint32_t u;
    asm("cvt.rna.tf32.f32 %0, %1;" : "=r"(u) : "f"(x));
    return __uint_as_float(u);
}
__device__ __forceinline__ float softplus_f(float r) {
    return (r > 15.0f) ? r : log1pf(__expf(r));
}
__device__ __forceinline__ uint32_t smem_u32_of(const void* p) {
    uint32_t a;
    asm("{ .reg .u64 t; cvta.to.shared.u64 t, %1; cvt.u32.u64 %0, t; }"
        : "=r"(a) : "l"(p));
    return a;
}
__device__ __forceinline__ void cp16(uint32_t dst, const void* src) {
    asm volatile("cp.async.cg.shared.global [%0], [%1], 16;"
                 :: "r"(dst), "l"(src) : "memory");
}
__device__ __forceinline__ void cp_commit() {
    asm volatile("cp.async.commit_group;" ::: "memory");
}
__device__ __forceinline__ void cp_wait1() {
    asm volatile("cp.async.wait_group 1;" ::: "memory");
}
__device__ __forceinline__ void mma_tf32(float* c, uint32_t a0, uint32_t a1,
                                         uint32_t a2, uint32_t a3,
                                         uint32_t b0, uint32_t b1) {
    asm volatile(
        "mma.sync.aligned.m16n8k8.row.col.f32.tf32.tf32.f32 "
        "{%0,%1,%2,%3}, {%4,%5,%6,%7}, {%8,%9}, {%0,%1,%2,%3};"
        : "+f"(c[0]), "+f"(c[1]), "+f"(c[2]), "+f"(c[3])
        : "r"(a0), "r"(a1), "r"(a2), "r"(a3), "r"(b0), "r"(b1));
}

// ---------------------------------------------------------------------------
// Prep 1: x -> tf32-rounded, k-permuted copy (same global layout otherwise)
// One thread per 32-k group.
// ---------------------------------------------------------------------------
__global__ __launch_bounds__(256)
void prep_x_kernel(const float* __restrict__ x) {
    size_t g = (size_t)blockIdx.x * 256 + threadIdx.x;  // group id
    const float* src = x + g * 32;
    float* dst = g_Xs + g * 32;
    float in[32], outv[32];
#pragma unroll
    for (int i = 0; i < 8; i++)
        *reinterpret_cast<float4*>(&in[i * 4]) =
            *reinterpret_cast<const float4*>(&src[i * 4]);
#pragma unroll
    for (int k = 0; k < 32; k++)
        outv[(k & 3) * 8 + (k >> 2)] = tf32_rna(in[k]);
#pragma unroll
    for (int i = 0; i < 8; i++)
        *reinterpret_cast<float4*>(&dst[i * 4]) =
            *reinterpret_cast<float4*>(&outv[i * 4]);
}

// ---------------------------------------------------------------------------
// Prep 2: W = mu + softplus(rho)*eps, transpose [I,O] -> [O,I], round, permute.
// Block handles a 32(k) x 256(o) tile.
// ---------------------------------------------------------------------------
__global__ __launch_bounds__(256)
void prep_w_kernel(const float* __restrict__ mu, const float* __restrict__ rho,
                   const float* __restrict__ eps) {
    __shared__ float tile[32][257];  // [k_local][o_local]
    const int kc = blockIdx.x, ot = blockIdx.y, m = blockIdx.z;
    const int t = threadIdx.x;
    const size_t base =
        (size_t)m * I_DIM * O_DIM + (size_t)kc * 32 * O_DIM + (size_t)ot * 256 + t;
#pragma unroll 4
    for (int kl = 0; kl < 32; kl++) {
        size_t idx = base + (size_t)kl * O_DIM;
        float w = fmaf(softplus_f(rho[idx]), eps[idx], mu[idx]);
        tile[kl][t] = tf32_rna(w);
    }
    __syncthreads();
    // write: chunk c -> o = c/8, j = c%8; gather permuted k for float4
#pragma unroll
    for (int i = 0; i < 8; i++) {
        int c = t + i * 256;
        int o = c >> 3, j = c & 7;
        float4 v;
        float* vp = reinterpret_cast<float*>(&v);
#pragma unroll
        for (int l = 0; l < 4; l++) {
            int kp = j * 4 + l;                       // permuted index k'
            int k = ((kp & 7) << 2) + (kp >> 3);      // original k
            vp[l] = tile[k][o];
        }
        float* dst = g_Ws + ((size_t)m * O_DIM + (size_t)ot * 256 + o) * I_DIM +
                     kc * 32 + j * 4;
        *reinterpret_cast<float4*>(dst) = v;
    }
}

__global__ void prep_b_kernel(const float* __restrict__ mu,
                              const float* __restrict__ rho,
                              const float* __restrict__ eps, int n) {
    int i = blockIdx.x * blockDim.x + threadIdx.x;
    if (i < n) g_bias[i] = fmaf(softplus_f(rho[i]), eps[i], mu[i]);
}

// ---------------------------------------------------------------------------
// GEMM: tf32 mma.sync.m16n8k8, 8 warps (2m x 4n), warp tile 64x64,
// 3-stage cp.async pipeline.
// ---------------------------------------------------------------------------
__global__ __launch_bounds__(256, 1)
void gemm_kernel(float* __restrict__ Out) {
    extern __shared__ float sm[];
    const uint32_t sbase = smem_u32_of(sm);
    const int tid = threadIdx.x, lane = tid & 31, wid = tid >> 5;
    const int gid = lane >> 2, tig = lane & 3;
    const int wm = wid >> 2, wn = wid & 3;   // 2 x 4 warp grid
    const int ot = blockIdx.x, bt = blockIdx.y, m = blockIdx.z;

    const float* Ag = g_Xs + ((size_t)m * B_DIM + (size_t)bt * CT_M) * I_DIM;
    const float* Bg = g_Ws + ((size_t)m * O_DIM + (size_t)ot * CT_N) * I_DIM;

    float acc[4][8][4];
#pragma unroll
    for (int f = 0; f < 4; f++)
#pragma unroll
        for (int n = 0; n < 8; n++)
#pragma unroll
            for (int q = 0; q < 4; q++) acc[f][n][q] = 0.0f;

    // ---- async stage loader ----
    auto load_stage = [&](int kt, int s) {
        const uint32_t sa = sbase + (uint32_t)s * STAGE_F * 4;
        const float* a = Ag + kt * CT_K;
#pragma unroll
        for (int i = 0; i < 4; i++) {              // A: 1024 x 16B
            int c = tid + i * 256;
            int r = c >> 3, j = c & 7;
            cp16(sa + (uint32_t)(r * PAD + j * 4) * 4,
                 a + (size_t)r * I_DIM + j * 4);
        }
        const uint32_t sb = sa + A_ST * 4;
        const float* b = Bg + kt * CT_K;
#pragma unroll
        for (int i = 0; i < 8; i++) {              // B: 2048 x 16B
            int c = tid + i * 256;
            int r = c >> 3, j = c & 7;
            cp16(sb + (uint32_t)(r * PAD + j * 4) * 4,
                 b + (size_t)r * I_DIM + j * 4);
        }
        cp_commit();
    };

    load_stage(0, 0);
    load_stage(1, 1);

    const int NKT = I_DIM / CT_K;  // 64
    for (int kt = 0; kt < NKT; kt++) {
        const int s = kt % STAGES;
        cp_wait1();
        __syncthreads();
        if (kt + 2 < NKT) load_stage(kt + 2, (kt + 2) % STAGES);

        const float* As = sm + (size_t)s * STAGE_F;
        const float* Bs = As + A_ST;

#pragma unroll
        for (int h = 0; h < 2; h++) {   // two halves of the 32-K tile
            float4 aLo[4], aHi[4], bV[8];
#pragma unroll
            for (int f = 0; f < 4; f++) {
                int r = wm * 64 + f * 16 + gid;
                aLo[f] = *reinterpret_cast<const float4*>(
                    &As[r * PAD + tig * 8 + 4 * h]);
                aHi[f] = *reinterpret_cast<const float4*>(
                    &As[(r + 8) * PAD + tig * 8 + 4 * h]);
            }
#pragma unroll
            for (int n = 0; n < 8; n++) {
                int r = wn * 64 + n * 8 + gid;
                bV[n] = *reinterpret_cast<const float4*>(
                    &Bs[r * PAD + tig * 8 + 4 * h]);
            }
#pragma unroll
            for (int w = 0; w < 2; w++) {   // two k8 windows per half
#pragma unroll
                for (int f = 0; f < 4; f++) {
                    uint32_t a0 = __float_as_uint(w ? aLo[f].z : aLo[f].x);
                    uint32_t a2 = __float_as_uint(w ? aLo[f].w : aLo[f].y);
                    uint32_t a1 = __float_as_uint(w ? aHi[f].z : aHi[f].x);
                    uint32_t a3 = __float_as_uint(w ? aHi[f].w : aHi[f].y);
#pragma unroll
                    for (int n = 0; n < 8; n++) {
                        uint32_t b0 = __float_as_uint(w ? bV[n].z : bV[n].x);
                        uint32_t b1 = __float_as_uint(w ? bV[n].w : bV[n].y);
                        mma_tf32(acc[f][n], a0, a1, a2, a3, b0, b1);
                    }
                }
            }
        }
        // next iteration's __syncthreads (after cp_wait1) protects stage reuse
    }

    // ---- epilogue: add bias, write out ----
    const float* bias = g_bias + m * O_DIM + ot * CT_N;
    const size_t rowbase = (size_t)m * B_DIM + (size_t)bt * CT_M;
#pragma unroll
    for (int f = 0; f < 4; f++) {
        int r0 = wm * 64 + f * 16 + gid;
#pragma unroll
        for (int n = 0; n < 8; n++) {
            int col = wn * 64 + n * 8 + tig * 2;
            float2 bb = *reinterpret_cast<const float2*>(&bias[col]);
            float2 v0, v1;
            v0.x = acc[f][n][0] + bb.x;
            v0.y = acc[f][n][1] + bb.y;
            v1.x = acc[f][n][2] + bb.x;
            v1.y = acc[f][n][3] + bb.y;
            *reinterpret_cast<float2*>(
                &Out[(rowbase + r0) * O_DIM + (size_t)ot * CT_N + col]) = v0;
            *reinterpret_cast<float2*>(
                &Out[(rowbase + r0 + 8) * O_DIM + (size_t)ot * CT_N + col]) = v1;
        }
    }
}

// ---------------------------------------------------------------------------
// Launch. Inputs: x, weight_mu, weight_rho, bias_mu, bias_rho, eps_w, eps_b
// ---------------------------------------------------------------------------
extern "C" void kernel_launch(void* const* d_in, const int* in_sizes, int n_in,
                              void* d_out, int out_size) {
    const float* x     = (const float*)d_in[0];
    const float* w_mu  = (const float*)d_in[1];
    const float* w_rho = (const float*)d_in[2];
    const float* b_mu  = (const float*)d_in[3];
    const float* b_rho = (const float*)d_in[4];
    const float* eps_w = (const float*)d_in[5];
    const float* eps_b = (const float*)d_in[6];
    float* out = (float*)d_out;

    cudaFuncSetAttribute(gemm_kernel, cudaFuncAttributeMaxDynamicSharedMemorySize,
                         SMEM_BYTES);

    // x groups: 8*4096*2048/32 = 2,097,152 -> 8192 blocks of 256
    prep_x_kernel<<<8192, 256>>>(x);
    prep_w_kernel<<<dim3(I_DIM / 32, O_DIM / 256, M_ENS), 256>>>(w_mu, w_rho, eps_w);
    int nb = M_ENS * O_DIM;
    prep_b_kernel<<<(nb + 255) / 256, 256>>>(b_mu, b_rho, eps_b, nb);

    gemm_kernel<<<dim3(O_DIM / CT_N, B_DIM / CT_M, M_ENS), 256, SMEM_BYTES>>>(out);
}

// round 5
// speedup vs baseline: 5.9800x; 2.0011x over previous
#include <cuda_runtime.h>
#include <cuda_fp16.h>
#include <cstdint>

// ---------------------------------------------------------------------------
// Problem shape
// ---------------------------------------------------------------------------
constexpr int M_ENS = 8, B_DIM = 4096, I_DIM = 2048, O_DIM = 2048;

// GEMM tiling: CTA = 128 (batch rows) x 256 (out cols), K-tile 64 (fp16).
constexpr int CT_M = 128, CT_N = 256, CT_K = 64;
constexpr int A_BYTES = CT_M * CT_K * 2;      // 16384
constexpr int B_BYTES = CT_N * CT_K * 2;      // 32768
constexpr int STAGE_BYTES = A_BYTES + B_BYTES;  // 49152
constexpr int STAGES = 4;
constexpr int SMEM_BYTES = STAGES * STAGE_BYTES;  // 196608

// ---------------------------------------------------------------------------
// Scratch (device globals; no cudaMalloc allowed).
// Global staged layout: row-major [rows][2048 k] fp16, with k permuted within
// every 32-k block: position p = t*8+u holds original k = 2t + (u&1)
// + ((u>>1)&1)*8 + ((u>>2)&1)*16, t=0..3. This makes each mma thread's
// fragment halves contiguous: granule t of a 32-block is exactly thread
// (tig=t)'s 8 halves for both k16 groups.
// ---------------------------------------------------------------------------
__device__ __align__(128) __half g_Xs[(size_t)M_ENS * B_DIM * I_DIM];
__device__ __align__(128) __half g_Ws[(size_t)M_ENS * O_DIM * I_DIM];
__device__ float g_bias[M_ENS * O_DIM];

// ---------------------------------------------------------------------------
// Helpers
// ---------------------------------------------------------------------------
__device__ __forceinline__ float softplus_f(float r) {
    return (r > 15.0f) ? r : log1pf(__expf(r));
}
__device__ __forceinline__ uint32_t smem_u32_of(const void* p) {
    uint32_t a;
    asm("{ .reg .u64 t; cvta.to.shared.u64 t, %1; cvt.u32.u64 %0, t; }"
        : "=r"(a) : "l"(p));
    return a;
}
__device__ __forceinline__ void cp16(uint32_t dst, const void* src) {
    asm volatile("cp.async.cg.shared.global [%0], [%1], 16;"
                 :: "r"(dst), "l"(src) : "memory");
}
__device__ __forceinline__ void cp_commit() {
    asm volatile("cp.async.commit_group;" ::: "memory");
}
__device__ __forceinline__ void cp_wait2() {
    asm volatile("cp.async.wait_group 2;" ::: "memory");
}
__device__ __forceinline__ uint32_t rev3(uint32_t x) {  // bit-reverse 3 bits
    return ((x & 1u) << 2) | (x & 2u) | ((x >> 2) & 1u);
}
__device__ __forceinline__ void mma_f16(float* c, uint32_t a0, uint32_t a1,
                                        uint32_t a2, uint32_t a3,
                                        uint32_t b0, uint32_t b1) {
    asm volatile(
        "mma.sync.aligned.m16n8k16.row.col.f32.f16.f16.f32 "
        "{%0,%1,%2,%3}, {%4,%5,%6,%7}, {%8,%9}, {%0,%1,%2,%3};"
        : "+f"(c[0]), "+f"(c[1]), "+f"(c[2]), "+f"(c[3])
        : "r"(a0), "r"(a1), "r"(a2), "r"(a3), "r"(b0), "r"(b1));
}

// ---------------------------------------------------------------------------
// Prep 1: x -> fp16, k-permuted. One thread per 32-k group.
// ---------------------------------------------------------------------------
__global__ __launch_bounds__(256)
void prep_x_kernel(const float* __restrict__ x) {
    size_t g = (size_t)blockIdx.x * 256 + threadIdx.x;
    const float* src = x + g * 32;
    __half* dst = g_Xs + g * 32;
    float in[32];
#pragma unroll
    for (int i = 0; i < 8; i++)
        *reinterpret_cast<float4*>(&in[i * 4]) =
            *reinterpret_cast<const float4*>(&src[i * 4]);
    __half out[32];
#pragma unroll
    for (int k = 0; k < 32; k++) {
        int t = (k >> 1) & 3;
        int u = (k & 1) | (((k >> 3) & 1) << 1) | (((k >> 4) & 1) << 2);
        out[t * 8 + u] = __float2half_rn(in[k]);
    }
#pragma unroll
    for (int i = 0; i < 4; i++)
        reinterpret_cast<uint4*>(dst)[i] = reinterpret_cast<uint4*>(out)[i];
}

// ---------------------------------------------------------------------------
// Prep 2: W = mu + softplus(rho)*eps, transpose [I,O]->[O,I], fp16, permute.
// Block handles a 32(k) x 256(o) tile.
// ---------------------------------------------------------------------------
__global__ __launch_bounds__(256)
void prep_w_kernel(const float* __restrict__ mu, const float* __restrict__ rho,
                   const float* __restrict__ eps) {
    __shared__ float tile[32][257];
    const int kc = blockIdx.x, ot = blockIdx.y, m = blockIdx.z;
    const int tt = threadIdx.x;
    const size_t base =
        (size_t)m * I_DIM * O_DIM + (size_t)kc * 32 * O_DIM + (size_t)ot * 256 + tt;
#pragma unroll 4
    for (int kl = 0; kl < 32; kl++) {
        size_t idx = base + (size_t)kl * O_DIM;
        tile[kl][tt] = fmaf(softplus_f(rho[idx]), eps[idx], mu[idx]);
    }
    __syncthreads();
    __half h[32];
#pragma unroll
    for (int p = 0; p < 32; p++) {
        int t = p >> 3, u = p & 7;
        int k = 2 * t + (u & 1) + (((u >> 1) & 1) << 3) + (((u >> 2) & 1) << 4);
        h[p] = __float2half_rn(tile[k][tt]);
    }
    __half* dst = g_Ws + ((size_t)m * O_DIM + (size_t)ot * 256 + tt) * I_DIM + kc * 32;
#pragma unroll
    for (int i = 0; i < 4; i++)
        reinterpret_cast<uint4*>(dst)[i] = reinterpret_cast<uint4*>(h)[i];
}

__global__ void prep_b_kernel(const float* __restrict__ mu,
                              const float* __restrict__ rho,
                              const float* __restrict__ eps, int n) {
    int i = blockIdx.x * blockDim.x + threadIdx.x;
    if (i < n) g_bias[i] = fmaf(softplus_f(rho[i]), eps[i], mu[i]);
}

// ---------------------------------------------------------------------------
// GEMM: fp16 mma.sync.m16n8k16, 8 warps (2m x 4n), warp tile 64x64,
// 4-stage cp.async pipeline, XOR(rev3) smem swizzle (conflict-free LDS.128).
// ---------------------------------------------------------------------------
__global__ __launch_bounds__(256, 1)
void gemm_kernel(float* __restrict__ Out) {
    extern __shared__ __align__(128) uint8_t sm[];
    const uint32_t sbase = smem_u32_of(sm);
    const int tid = threadIdx.x, lane = tid & 31, wid = tid >> 5;
    const int gid = lane >> 2, tig = lane & 3;
    const int wm = wid >> 2, wn = wid & 3;
    const int ot = blockIdx.x, bt = blockIdx.y, m = blockIdx.z;

    const __half* Ag = g_Xs + ((size_t)m * B_DIM + (size_t)bt * CT_M) * I_DIM;
    const __half* Bg = g_Ws + ((size_t)m * O_DIM + (size_t)ot * CT_N) * I_DIM;

    float acc[4][8][4];
#pragma unroll
    for (int f = 0; f < 4; f++)
#pragma unroll
        for (int n = 0; n < 8; n++)
#pragma unroll
            for (int q = 0; q < 4; q++) acc[f][n][q] = 0.0f;

    auto load_stage = [&](int kt, int s) {
        const uint32_t sa = sbase + (uint32_t)s * STAGE_BYTES;
#pragma unroll
        for (int i = 0; i < 4; i++) {       // A: 1024 x 16B
            int c = tid + i * 256;
            int r = c >> 3, j = c & 7;
            cp16(sa + (uint32_t)(r * 128 + (((uint32_t)j ^ rev3(r & 7)) << 4)),
                 Ag + (size_t)r * I_DIM + kt * 64 + j * 8);
        }
        const uint32_t sbB = sa + A_BYTES;
#pragma unroll
        for (int i = 0; i < 8; i++) {       // B: 2048 x 16B
            int c = tid + i * 256;
            int r = c >> 3, j = c & 7;
            cp16(sbB + (uint32_t)(r * 128 + (((uint32_t)j ^ rev3(r & 7)) << 4)),
                 Bg + (size_t)r * I_DIM + kt * 64 + j * 8);
        }
        cp_commit();
    };

    load_stage(0, 0);
    load_stage(1, 1);
    load_stage(2, 2);

    const int NKT = I_DIM / CT_K;  // 32
    const uint32_t arev = rev3(gid) << 4;

    for (int kt = 0; kt < NKT; kt++) {
        const int s = kt & 3;
        cp_wait2();
        __syncthreads();
        if (kt + 3 < NKT) load_stage(kt + 3, (kt + 3) & 3);

        const uint8_t* As = sm + (size_t)s * STAGE_BYTES;
        const uint8_t* Bs = As + A_BYTES;

#pragma unroll
        for (int kb = 0; kb < 2; kb++) {    // two 32-k blocks in the tile
            const uint32_t gran = (((uint32_t)(kb * 4 + tig)) << 4) ^ arev;
            uint4 aLo[4], aHi[4], bV[8];
#pragma unroll
            for (int f = 0; f < 4; f++) {
                int r = wm * 64 + f * 16 + gid;
                aLo[f] = *reinterpret_cast<const uint4*>(As + r * 128 + gran);
                aHi[f] = *reinterpret_cast<const uint4*>(As + (r + 8) * 128 + gran);
            }
#pragma unroll
            for (int n = 0; n < 8; n++) {
                int r = wn * 64 + n * 8 + gid;
                bV[n] = *reinterpret_cast<const uint4*>(Bs + r * 128 + gran);
            }
#pragma unroll
            for (int kg = 0; kg < 2; kg++) {  // two k16 groups per 32-block
#pragma unroll
                for (int f = 0; f < 4; f++) {
                    uint32_t a0 = kg ? aLo[f].z : aLo[f].x;
                    uint32_t a2 = kg ? aLo[f].w : aLo[f].y;
                    uint32_t a1 = kg ? aHi[f].z : aHi[f].x;
                    uint32_t a3 = kg ? aHi[f].w : aHi[f].y;
#pragma unroll
                    for (int n = 0; n < 8; n++) {
                        uint32_t b0 = kg ? bV[n].z : bV[n].x;
                        uint32_t b1 = kg ? bV[n].w : bV[n].y;
                        mma_f16(acc[f][n], a0, a1, a2, a3, b0, b1);
                    }
                }
            }
        }
    }

    // ---- epilogue: add bias, write out ----
    const float* bias = g_bias + m * O_DIM + ot * CT_N;
    const size_t rowbase = (size_t)m * B_DIM + (size_t)bt * CT_M;
#pragma unroll
    for (int f = 0; f < 4; f++) {
        int r0 = wm * 64 + f * 16 + gid;
#pragma unroll
        for (int n = 0; n < 8; n++) {
            int col = wn * 64 + n * 8 + tig * 2;
            float2 bb = *reinterpret_cast<const float2*>(&bias[col]);
            float2 v0, v1;
            v0.x = acc[f][n][0] + bb.x;
            v0.y = acc[f][n][1] + bb.y;
            v1.x = acc[f][n][2] + bb.x;
            v1.y = acc[f][n][3] + bb.y;
            *reinterpret_cast<float2*>(
                &Out[(rowbase + r0) * O_DIM + (size_t)ot * CT_N + col]) = v0;
            *reinterpret_cast<float2*>(
                &Out[(rowbase + r0 + 8) * O_DIM + (size_t)ot * CT_N + col]) = v1;
        }
    }
}

// ---------------------------------------------------------------------------
// Launch. Inputs: x, weight_mu, weight_rho, bias_mu, bias_rho, eps_w, eps_b
// ---------------------------------------------------------------------------
extern "C" void kernel_launch(void* const* d_in, const int* in_sizes, int n_in,
                              void* d_out, int out_size) {
    const float* x     = (const float*)d_in[0];
    const float* w_mu  = (const float*)d_in[1];
    const float* w_rho = (const float*)d_in[2];
    const float* b_mu  = (const float*)d_in[3];
    const float* b_rho = (const float*)d_in[4];
    const float* eps_w = (const float*)d_in[5];
    const float* eps_b = (const float*)d_in[6];
    float* out = (float*)d_out;

    cudaFuncSetAttribute(gemm_kernel, cudaFuncAttributeMaxDynamicSharedMemorySize,
                         SMEM_BYTES);

    prep_x_kernel<<<8192, 256>>>(x);   // 2,097,152 groups / 256
    prep_w_kernel<<<dim3(I_DIM / 32, O_DIM / 256, M_ENS), 256>>>(w_mu, w_rho, eps_w);
    int nb = M_ENS * O_DIM;
    prep_b_kernel<<<(nb + 255) / 256, 256>>>(b_mu, b_rho, eps_b, nb);

    gemm_kernel<<<dim3(O_DIM / CT_N, B_DIM / CT_M, M_ENS), 256, SMEM_BYTES>>>(out);
}

// round 6
// speedup vs baseline: 6.4340x; 1.0759x over previous
#include <cuda_runtime.h>
#include <cuda_fp16.h>
#include <cstdint>

// ---------------------------------------------------------------------------
// Problem shape
// ---------------------------------------------------------------------------
constexpr int M_ENS = 8, B_DIM = 4096, I_DIM = 2048, O_DIM = 2048;

// GEMM tiling: CTA = 128 (batch rows) x 128 (out cols), K-tile 64 (fp16),
// 128 threads (4 warps, 2x2), 2 CTAs/SM.
constexpr int CT_M = 128, CT_N = 128, CT_K = 64;
constexpr int A_BYTES = CT_M * CT_K * 2;        // 16384
constexpr int B_BYTES = CT_N * CT_K * 2;        // 16384
constexpr int STAGE_BYTES = A_BYTES + B_BYTES;  // 32768
constexpr int STAGES = 3;
constexpr int SMEM_BYTES = STAGES * STAGE_BYTES;  // 98304 per CTA (x2 = 192K/SM)

// ---------------------------------------------------------------------------
// Scratch (device globals; no cudaMalloc allowed).
// Staged layout: row-major [rows][2048 k] fp16, k permuted within every
// 32-k block: position p = t*8+u holds original k = 2t + (u&1)
// + ((u>>1)&1)*8 + ((u>>2)&1)*16, t=0..3 -> each mma thread's fragment
// halves are contiguous 16B granules.
// ---------------------------------------------------------------------------
__device__ __align__(128) __half g_Xs[(size_t)M_ENS * B_DIM * I_DIM];
__device__ __align__(128) __half g_Ws[(size_t)M_ENS * O_DIM * I_DIM];
__device__ float g_bias[M_ENS * O_DIM];

// ---------------------------------------------------------------------------
// Helpers
// ---------------------------------------------------------------------------
__device__ __forceinline__ float softplus_f(float r) {
    return (r > 15.0f) ? r : log1pf(__expf(r));
}
__device__ __forceinline__ uint32_t smem_u32_of(const void* p) {
    uint32_t a;
    asm("{ .reg .u64 t; cvta.to.shared.u64 t, %1; cvt.u32.u64 %0, t; }"
        : "=r"(a) : "l"(p));
    return a;
}
__device__ __forceinline__ void cp16(uint32_t dst, const void* src) {
    asm volatile("cp.async.cg.shared.global [%0], [%1], 16;"
                 :: "r"(dst), "l"(src) : "memory");
}
__device__ __forceinline__ void cp_commit() {
    asm volatile("cp.async.commit_group;" ::: "memory");
}
__device__ __forceinline__ void cp_wait1() {
    asm volatile("cp.async.wait_group 1;" ::: "memory");
}
__device__ __forceinline__ uint32_t rev3(uint32_t x) {  // bit-reverse 3 bits
    return ((x & 1u) << 2) | (x & 2u) | ((x >> 2) & 1u);
}
__device__ __forceinline__ void mma_f16(float* c, uint32_t a0, uint32_t a1,
                                        uint32_t a2, uint32_t a3,
                                        uint32_t b0, uint32_t b1) {
    asm volatile(
        "mma.sync.aligned.m16n8k16.row.col.f32.f16.f16.f32 "
        "{%0,%1,%2,%3}, {%4,%5,%6,%7}, {%8,%9}, {%0,%1,%2,%3};"
        : "+f"(c[0]), "+f"(c[1]), "+f"(c[2]), "+f"(c[3])
        : "r"(a0), "r"(a1), "r"(a2), "r"(a3), "r"(b0), "r"(b1));
}

// ---------------------------------------------------------------------------
// Prep 1: x -> fp16, k-permuted. One thread per 32-k group.
// ---------------------------------------------------------------------------
__global__ __launch_bounds__(256)
void prep_x_kernel(const float* __restrict__ x) {
    size_t g = (size_t)blockIdx.x * 256 + threadIdx.x;
    const float* src = x + g * 32;
    __half* dst = g_Xs + g * 32;
    float in[32];
#pragma unroll
    for (int i = 0; i < 8; i++)
        *reinterpret_cast<float4*>(&in[i * 4]) =
            *reinterpret_cast<const float4*>(&src[i * 4]);
    __half out[32];
#pragma unroll
    for (int k = 0; k < 32; k++) {
        int t = (k >> 1) & 3;
        int u = (k & 1) | (((k >> 3) & 1) << 1) | (((k >> 4) & 1) << 2);
        out[t * 8 + u] = __float2half_rn(in[k]);
    }
#pragma unroll
    for (int i = 0; i < 4; i++)
        reinterpret_cast<uint4*>(dst)[i] = reinterpret_cast<uint4*>(out)[i];
}

// ---------------------------------------------------------------------------
// Prep 2: W = mu + softplus(rho)*eps, transpose [I,O]->[O,I], fp16, permute.
// Block handles a 32(k) x 256(o) tile.
// ---------------------------------------------------------------------------
__global__ __launch_bounds__(256)
void prep_w_kernel(const float* __restrict__ mu, const float* __restrict__ rho,
                   const float* __restrict__ eps) {
    __shared__ float tile[32][257];
    const int kc = blockIdx.x, ot = blockIdx.y, m = blockIdx.z;
    const int tt = threadIdx.x;
    const size_t base =
        (size_t)m * I_DIM * O_DIM + (size_t)kc * 32 * O_DIM + (size_t)ot * 256 + tt;
#pragma unroll 4
    for (int kl = 0; kl < 32; kl++) {
        size_t idx = base + (size_t)kl * O_DIM;
        tile[kl][tt] = fmaf(softplus_f(rho[idx]), eps[idx], mu[idx]);
    }
    __syncthreads();
    __half h[32];
#pragma unroll
    for (int p = 0; p < 32; p++) {
        int t = p >> 3, u = p & 7;
        int k = 2 * t + (u & 1) + (((u >> 1) & 1) << 3) + (((u >> 2) & 1) << 4);
        h[p] = __float2half_rn(tile[k][tt]);
    }
    __half* dst = g_Ws + ((size_t)m * O_DIM + (size_t)ot * 256 + tt) * I_DIM + kc * 32;
#pragma unroll
    for (int i = 0; i < 4; i++)
        reinterpret_cast<uint4*>(dst)[i] = reinterpret_cast<uint4*>(h)[i];
}

__global__ void prep_b_kernel(const float* __restrict__ mu,
                              const float* __restrict__ rho,
                              const float* __restrict__ eps, int n) {
    int i = blockIdx.x * blockDim.x + threadIdx.x;
    if (i < n) g_bias[i] = fmaf(softplus_f(rho[i]), eps[i], mu[i]);
}

// ---------------------------------------------------------------------------
// GEMM: fp16 mma.sync.m16n8k16, 4 warps (2m x 2n), warp tile 64x64,
// 3-stage cp.async pipeline, XOR(rev3) smem swizzle, 2 CTAs/SM.
// ---------------------------------------------------------------------------
__global__ __launch_bounds__(128, 2)
void gemm_kernel(float* __restrict__ Out) {
    extern __shared__ __align__(128) uint8_t sm[];
    const uint32_t sbase = smem_u32_of(sm);
    const int tid = threadIdx.x, lane = tid & 31, wid = tid >> 5;
    const int gid = lane >> 2, tig = lane & 3;
    const int wm = wid >> 1, wn = wid & 1;   // 2 x 2 warp grid
    const int ot = blockIdx.x, bt = blockIdx.y, m = blockIdx.z;

    const __half* Ag = g_Xs + ((size_t)m * B_DIM + (size_t)bt * CT_M) * I_DIM;
    const __half* Bg = g_Ws + ((size_t)m * O_DIM + (size_t)ot * CT_N) * I_DIM;

    float acc[4][8][4];
#pragma unroll
    for (int f = 0; f < 4; f++)
#pragma unroll
        for (int n = 0; n < 8; n++)
#pragma unroll
            for (int q = 0; q < 4; q++) acc[f][n][q] = 0.0f;

    auto load_stage = [&](int kt, int s) {
        const uint32_t sa = sbase + (uint32_t)s * STAGE_BYTES;
#pragma unroll
        for (int i = 0; i < 8; i++) {       // A: 1024 x 16B over 128 threads
            int c = tid + i * 128;
            int r = c >> 3, j = c & 7;
            cp16(sa + (uint32_t)(r * 128 + (((uint32_t)j ^ rev3(r & 7)) << 4)),
                 Ag + (size_t)r * I_DIM + kt * 64 + j * 8);
        }
        const uint32_t sbB = sa + A_BYTES;
#pragma unroll
        for (int i = 0; i < 8; i++) {       // B: 1024 x 16B
            int c = tid + i * 128;
            int r = c >> 3, j = c & 7;
            cp16(sbB + (uint32_t)(r * 128 + (((uint32_t)j ^ rev3(r & 7)) << 4)),
                 Bg + (size_t)r * I_DIM + kt * 64 + j * 8);
        }
        cp_commit();
    };

    load_stage(0, 0);
    load_stage(1, 1);

    const int NKT = I_DIM / CT_K;  // 32
    const uint32_t arev = rev3(gid) << 4;

    for (int kt = 0; kt < NKT; kt++) {
        const int s = kt % STAGES;
        cp_wait1();
        __syncthreads();
        if (kt + 2 < NKT) load_stage(kt + 2, (kt + 2) % STAGES);

        const uint8_t* As = sm + (size_t)s * STAGE_BYTES;
        const uint8_t* Bs = As + A_BYTES;

#pragma unroll
        for (int kb = 0; kb < 2; kb++) {    // two 32-k blocks per tile
            const uint32_t gran = (((uint32_t)(kb * 4 + tig)) << 4) ^ arev;
            uint4 aLo[4], aHi[4], bV[8];
#pragma unroll
            for (int f = 0; f < 4; f++) {
                int r = wm * 64 + f * 16 + gid;
                aLo[f] = *reinterpret_cast<const uint4*>(As + r * 128 + gran);
                aHi[f] = *reinterpret_cast<const uint4*>(As + (r + 8) * 128 + gran);
            }
#pragma unroll
            for (int n = 0; n < 8; n++) {
                int r = wn * 64 + n * 8 + gid;
                bV[n] = *reinterpret_cast<const uint4*>(Bs + r * 128 + gran);
            }
#pragma unroll
            for (int kg = 0; kg < 2; kg++) {  // two k16 groups per 32-block
#pragma unroll
                for (int f = 0; f < 4; f++) {
                    uint32_t a0 = kg ? aLo[f].z : aLo[f].x;
                    uint32_t a2 = kg ? aLo[f].w : aLo[f].y;
                    uint32_t a1 = kg ? aHi[f].z : aHi[f].x;
                    uint32_t a3 = kg ? aHi[f].w : aHi[f].y;
#pragma unroll
                    for (int n = 0; n < 8; n++) {
                        uint32_t b0 = kg ? bV[n].z : bV[n].x;
                        uint32_t b1 = kg ? bV[n].w : bV[n].y;
                        mma_f16(acc[f][n], a0, a1, a2, a3, b0, b1);
                    }
                }
            }
        }
    }

    // ---- epilogue: add bias, write out ----
    const float* bias = g_bias + m * O_DIM + ot * CT_N;
    const size_t rowbase = (size_t)m * B_DIM + (size_t)bt * CT_M;
#pragma unroll
    for (int f = 0; f < 4; f++) {
        int r0 = wm * 64 + f * 16 + gid;
#pragma unroll
        for (int n = 0; n < 8; n++) {
            int col = wn * 64 + n * 8 + tig * 2;
            float2 bb = *reinterpret_cast<const float2*>(&bias[col]);
            float2 v0, v1;
            v0.x = acc[f][n][0] + bb.x;
            v0.y = acc[f][n][1] + bb.y;
            v1.x = acc[f][n][2] + bb.x;
            v1.y = acc[f][n][3] + bb.y;
            *reinterpret_cast<float2*>(
                &Out[(rowbase + r0) * O_DIM + (size_t)ot * CT_N + col]) = v0;
            *reinterpret_cast<float2*>(
                &Out[(rowbase + r0 + 8) * O_DIM + (size_t)ot * CT_N + col]) = v1;
        }
    }
}

// ---------------------------------------------------------------------------
// Launch. Inputs: x, weight_mu, weight_rho, bias_mu, bias_rho, eps_w, eps_b
// ---------------------------------------------------------------------------
extern "C" void kernel_launch(void* const* d_in, const int* in_sizes, int n_in,
                              void* d_out, int out_size) {
    const float* x     = (const float*)d_in[0];
    const float* w_mu  = (const float*)d_in[1];
    const float* w_rho = (const float*)d_in[2];
    const float* b_mu  = (const float*)d_in[3];
    const float* b_rho = (const float*)d_in[4];
    const float* eps_w = (const float*)d_in[5];
    const float* eps_b = (const float*)d_in[6];
    float* out = (float*)d_out;

    cudaFuncSetAttribute(gemm_kernel, cudaFuncAttributeMaxDynamicSharedMemorySize,
                         SMEM_BYTES);

    prep_x_kernel<<<8192, 256>>>(x);   // 2,097,152 groups / 256
    prep_w_kernel<<<dim3(I_DIM / 32, O_DIM / 256, M_ENS), 256>>>(w_mu, w_rho, eps_w);
    int nb = M_ENS * O_DIM;
    prep_b_kernel<<<(nb + 255) / 256, 256>>>(b_mu, b_rho, eps_b, nb);

    gemm_kernel<<<dim3(O_DIM / CT_N, B_DIM / CT_M, M_ENS), 128, SMEM_BYTES>>>(out);
}

// round 7
// speedup vs baseline: 6.8326x; 1.0620x over previous
#include <cuda_runtime.h>
#include <cuda_fp16.h>
#include <cstdint>

// ---------------------------------------------------------------------------
// Problem shape
// ---------------------------------------------------------------------------
constexpr int M_ENS = 8, B_DIM = 4096, I_DIM = 2048, O_DIM = 2048;

// GEMM tiling: CTA = 128x128, K-tile 64, 4 warps (2x2), 2 CTAs/SM.
constexpr int CT_M = 128, CT_N = 128, CT_K = 64;
constexpr int NKT = I_DIM / CT_K;    // 32 k-tiles
constexpr int NBT = B_DIM / CT_M;    // 32 row tiles
constexpr int NOT16 = O_DIM / CT_N;  // 16 col tiles
constexpr int IMG_BYTES = CT_M * CT_K * 2;      // 16384 per operand image
constexpr int STAGE_BYTES = 2 * IMG_BYTES;      // 32768
constexpr int STAGES = 3;
constexpr int SMEM_CTRL = 128;                  // mbarriers live here
constexpr int SMEM_BYTES = SMEM_CTRL + STAGES * STAGE_BYTES;  // 98432/CTA

// ---------------------------------------------------------------------------
// Scratch: pre-swizzled smem IMAGES. Image(m,tile,kt) is the exact 16KB the
// gemm wants in shared memory: row r (128B) holds 8 granules; granule slot
// (j ^ rev3(r&7)) stores 8 halves u with k = 32*(j>>2) + 2*(j&3) + (u&1)
// + ((u>>1)&1)*8 + ((u>>2)&1)*16  (mma fragment order).
// ---------------------------------------------------------------------------
__device__ __align__(128) __half g_Xs[(size_t)M_ENS * B_DIM * I_DIM];
__device__ __align__(128) __half g_Ws[(size_t)M_ENS * O_DIM * I_DIM];
__device__ float g_bias[M_ENS * O_DIM];

// ---------------------------------------------------------------------------
// Helpers
// ---------------------------------------------------------------------------
__device__ __forceinline__ float softplus_f(float r) {
    return (r > 15.0f) ? r : log1pf(__expf(r));
}
__device__ __forceinline__ uint32_t smem_u32_of(const void* p) {
    uint32_t a;
    asm("{ .reg .u64 t; cvta.to.shared.u64 t, %1; cvt.u32.u64 %0, t; }"
        : "=r"(a) : "l"(p));
    return a;
}
__device__ __forceinline__ uint32_t rev3(uint32_t x) {
    return ((x & 1u) << 2) | (x & 2u) | ((x >> 2) & 1u);
}
__device__ __forceinline__ void mbar_init(uint32_t mbar, uint32_t cnt) {
    asm volatile("mbarrier.init.shared.b64 [%0], %1;" :: "r"(mbar), "r"(cnt) : "memory");
}
__device__ __forceinline__ void mbar_expect_tx(uint32_t mbar, uint32_t bytes) {
    asm volatile("mbarrier.arrive.expect_tx.shared.b64 _, [%0], %1;"
                 :: "r"(mbar), "r"(bytes) : "memory");
}
__device__ __forceinline__ void mbar_wait(uint32_t mbar, uint32_t parity) {
    asm volatile(
        "{\n\t.reg .pred P;\n\t"
        "W_%=:\n\t"
        "mbarrier.try_wait.parity.acquire.cta.shared::cta.b64 P, [%0], %1, 0x989680;\n\t"
        "@P bra.uni D_%=;\n\t"
        "bra.uni W_%=;\n\t"
        "D_%=:\n\t}"
        :: "r"(mbar), "r"(parity) : "memory");
}
__device__ __forceinline__ void bulk_g2s(uint32_t dst, const void* src,
                                         uint32_t bytes, uint32_t mbar) {
    asm volatile(
        "cp.async.bulk.shared::cluster.global.mbarrier::complete_tx::bytes "
        "[%0], [%1], %2, [%3];"
        :: "r"(dst), "l"(src), "r"(bytes), "r"(mbar) : "memory");
}
__device__ __forceinline__ void mma_f16(float* c, uint32_t a0, uint32_t a1,
                                        uint32_t a2, uint32_t a3,
                                        uint32_t b0, uint32_t b1) {
    asm volatile(
        "mma.sync.aligned.m16n8k16.row.col.f32.f16.f16.f32 "
        "{%0,%1,%2,%3}, {%4,%5,%6,%7}, {%8,%9}, {%0,%1,%2,%3};"
        : "+f"(c[0]), "+f"(c[1]), "+f"(c[2]), "+f"(c[3])
        : "r"(a0), "r"(a1), "r"(a2), "r"(a3), "r"(b0), "r"(b1));
}

// ---------------------------------------------------------------------------
// Prep 1: x -> fp16 smem images. One CTA (128 thr) per (m, bt, kt) image.
// ---------------------------------------------------------------------------
__global__ __launch_bounds__(128)
void prep_x_kernel(const float* __restrict__ x) {
    __shared__ float tile[128][68];
    const int g = blockIdx.x;
    const int kt = g & 31, bt = (g >> 5) & 31, m = g >> 10;
    const int t = threadIdx.x;
    const float* src = x + ((size_t)(m * B_DIM + bt * 128)) * I_DIM + kt * 64;
#pragma unroll
    for (int i = 0; i < 16; i++) {   // 128 rows x 64 floats, coalesced
        int c = t + i * 128;
        int r = c >> 4, q = c & 15;
        float4 v = *reinterpret_cast<const float4*>(src + (size_t)r * I_DIM + q * 4);
        *reinterpret_cast<float4*>(&tile[r][q * 4]) = v;
    }
    __syncthreads();
    const int r = t;
    const uint32_t rx = rev3((uint32_t)r & 7) << 4;
    char* dst = (char*)g_Xs +
                ((size_t)((m * NBT + bt) * NKT + kt)) * IMG_BYTES + r * 128;
#pragma unroll
    for (int j = 0; j < 8; j++) {
        int kb = j >> 2, tt = j & 3;
        __half h[8];
#pragma unroll
        for (int u = 0; u < 8; u++) {
            int k = kb * 32 + 2 * tt + (u & 1) + ((u >> 1) & 1) * 8 + ((u >> 2) & 1) * 16;
            h[u] = __float2half_rn(tile[r][k]);
        }
        *reinterpret_cast<uint4*>(dst + (((uint32_t)j << 4) ^ rx)) =
            *reinterpret_cast<uint4*>(h);
    }
}

// ---------------------------------------------------------------------------
// Prep 2: W = mu + softplus(rho)*eps, transpose [I,O]->[O,I], fp16 images.
// One CTA (128 thr) per (m, ot, kt) image.
// ---------------------------------------------------------------------------
__global__ __launch_bounds__(128)
void prep_w_kernel(const float* __restrict__ mu, const float* __restrict__ rho,
                   const float* __restrict__ eps) {
    __shared__ float tile[64][132];
    const int g = blockIdx.x;
    const int kt = g & 31, ot = (g >> 5) & 15, m = g >> 9;
    const int t = threadIdx.x;
    const size_t base =
        (size_t)m * I_DIM * O_DIM + (size_t)(kt * 64) * O_DIM + ot * 128;
#pragma unroll
    for (int i = 0; i < 16; i++) {   // 64 rows x 128 floats, coalesced
        int c = t + i * 128;
        int r = c >> 5, q = c & 31;
        size_t idx = base + (size_t)r * O_DIM + q * 4;
        float4 vm = *reinterpret_cast<const float4*>(mu + idx);
        float4 vr = *reinterpret_cast<const float4*>(rho + idx);
        float4 ve = *reinterpret_cast<const float4*>(eps + idx);
        float4 w;
        w.x = fmaf(softplus_f(vr.x), ve.x, vm.x);
        w.y = fmaf(softplus_f(vr.y), ve.y, vm.y);
        w.z = fmaf(softplus_f(vr.z), ve.z, vm.z);
        w.w = fmaf(softplus_f(vr.w), ve.w, vm.w);
        *reinterpret_cast<float4*>(&tile[r][q * 4]) = w;
    }
    __syncthreads();
    const int o = t;   // output row (O dim), reads column o of tile
    const uint32_t rx = rev3((uint32_t)o & 7) << 4;
    char* dst = (char*)g_Ws +
                ((size_t)((m * NOT16 + ot) * NKT + kt)) * IMG_BYTES + o * 128;
#pragma unroll
    for (int j = 0; j < 8; j++) {
        int kb = j >> 2, tt = j & 3;
        __half h[8];
#pragma unroll
        for (int u = 0; u < 8; u++) {
            int k = kb * 32 + 2 * tt + (u & 1) + ((u >> 1) & 1) * 8 + ((u >> 2) & 1) * 16;
            h[u] = __float2half_rn(tile[k][o]);
        }
        *reinterpret_cast<uint4*>(dst + (((uint32_t)j << 4) ^ rx)) =
            *reinterpret_cast<uint4*>(h);
    }
}

__global__ void prep_b_kernel(const float* __restrict__ mu,
                              const float* __restrict__ rho,
                              const float* __restrict__ eps, int n) {
    int i = blockIdx.x * blockDim.x + threadIdx.x;
    if (i < n) g_bias[i] = fmaf(softplus_f(rho[i]), eps[i], mu[i]);
}

// ---------------------------------------------------------------------------
// GEMM: fp16 mma.sync.m16n8k16, 4 warps (2x2), warp tile 64x64,
// 3-stage bulk-copy pipeline (single-thread issue, mbarrier), 2 CTAs/SM.
// ---------------------------------------------------------------------------
__global__ __launch_bounds__(128, 2)
void gemm_kernel(float* __restrict__ Out) {
    extern __shared__ __align__(128) uint8_t smem_raw[];
    const uint32_t sb = smem_u32_of(smem_raw);
    const int tid = threadIdx.x, lane = tid & 31, wid = tid >> 5;
    const int gid = lane >> 2, tig = lane & 3;
    const int wm = wid >> 1, wn = wid & 1;
    const int ot = blockIdx.x, bt = blockIdx.y, m = blockIdx.z;

    const char* gA = (const char*)g_Xs + (size_t)((m * NBT + bt) * NKT) * IMG_BYTES;
    const char* gB = (const char*)g_Ws + (size_t)((m * NOT16 + ot) * NKT) * IMG_BYTES;

    if (tid == 0) {
#pragma unroll
        for (int s = 0; s < STAGES; s++) mbar_init(sb + 8 * s, 1);
        asm volatile("fence.proxy.async.shared::cta;" ::: "memory");
    }
    __syncthreads();

    if (tid == 0) {
#pragma unroll
        for (int kt = 0; kt < 2; kt++) {
            uint32_t fb = sb + 8 * kt;
            uint32_t st = sb + SMEM_CTRL + kt * STAGE_BYTES;
            mbar_expect_tx(fb, STAGE_BYTES);
            bulk_g2s(st, gA + (size_t)kt * IMG_BYTES, IMG_BYTES, fb);
            bulk_g2s(st + IMG_BYTES, gB + (size_t)kt * IMG_BYTES, IMG_BYTES, fb);
        }
    }

    float acc[4][8][4];
#pragma unroll
    for (int f = 0; f < 4; f++)
#pragma unroll
        for (int n = 0; n < 8; n++)
#pragma unroll
            for (int q = 0; q < 4; q++) acc[f][n][q] = 0.0f;

    const uint32_t arev = rev3(gid) << 4;
    int s = 0, ph = 0;

    for (int kt = 0; kt < NKT; kt++) {
        mbar_wait(sb + 8 * s, ph);
        __syncthreads();   // all warps done reading stage (kt+2)%3's old data

        if (tid == 0 && kt + 2 < NKT) {
            int s2 = (s + 2 >= STAGES) ? s + 2 - STAGES : s + 2;
            uint32_t fb = sb + 8 * s2;
            uint32_t st = sb + SMEM_CTRL + s2 * STAGE_BYTES;
            mbar_expect_tx(fb, STAGE_BYTES);
            bulk_g2s(st, gA + (size_t)(kt + 2) * IMG_BYTES, IMG_BYTES, fb);
            bulk_g2s(st + IMG_BYTES, gB + (size_t)(kt + 2) * IMG_BYTES, IMG_BYTES, fb);
        }

        const uint8_t* As = smem_raw + SMEM_CTRL + s * STAGE_BYTES;
        const uint8_t* Bs = As + IMG_BYTES;

#pragma unroll
        for (int kb = 0; kb < 2; kb++) {
            const uint32_t gran = (((uint32_t)(kb * 4 + tig)) << 4) ^ arev;
            uint4 aLo[4], aHi[4], bV[8];
#pragma unroll
            for (int n = 0; n < 8; n++) {
                int r = wn * 64 + n * 8 + gid;
                bV[n] = *reinterpret_cast<const uint4*>(Bs + r * 128 + gran);
            }
#pragma unroll
            for (int f = 0; f < 4; f++) {
                int r = wm * 64 + f * 16 + gid;
                aLo[f] = *reinterpret_cast<const uint4*>(As + r * 128 + gran);
                aHi[f] = *reinterpret_cast<const uint4*>(As + (r + 8) * 128 + gran);
            }
#pragma unroll
            for (int kg = 0; kg < 2; kg++) {
#pragma unroll
                for (int f = 0; f < 4; f++) {
                    uint32_t a0 = kg ? aLo[f].z : aLo[f].x;
                    uint32_t a2 = kg ? aLo[f].w : aLo[f].y;
                    uint32_t a1 = kg ? aHi[f].z : aHi[f].x;
                    uint32_t a3 = kg ? aHi[f].w : aHi[f].y;
#pragma unroll
                    for (int n = 0; n < 8; n++) {
                        uint32_t b0 = kg ? bV[n].z : bV[n].x;
                        uint32_t b1 = kg ? bV[n].w : bV[n].y;
                        mma_f16(acc[f][n], a0, a1, a2, a3, b0, b1);
                    }
                }
            }
        }
        if (++s == STAGES) { s = 0; ph ^= 1; }
    }

    // ---- epilogue: add bias, write out ----
    const float* bias = g_bias + m * O_DIM + ot * CT_N;
    const size_t rowbase = (size_t)m * B_DIM + (size_t)bt * CT_M;
#pragma unroll
    for (int f = 0; f < 4; f++) {
        int r0 = wm * 64 + f * 16 + gid;
#pragma unroll
        for (int n = 0; n < 8; n++) {
            int col = wn * 64 + n * 8 + tig * 2;
            float2 bb = *reinterpret_cast<const float2*>(&bias[col]);
            float2 v0, v1;
            v0.x = acc[f][n][0] + bb.x;
            v0.y = acc[f][n][1] + bb.y;
            v1.x = acc[f][n][2] + bb.x;
            v1.y = acc[f][n][3] + bb.y;
            *reinterpret_cast<float2*>(
                &Out[(rowbase + r0) * O_DIM + (size_t)ot * CT_N + col]) = v0;
            *reinterpret_cast<float2*>(
                &Out[(rowbase + r0 + 8) * O_DIM + (size_t)ot * CT_N + col]) = v1;
        }
    }
}

// ---------------------------------------------------------------------------
// Launch. Inputs: x, weight_mu, weight_rho, bias_mu, bias_rho, eps_w, eps_b
// ---------------------------------------------------------------------------
extern "C" void kernel_launch(void* const* d_in, const int* in_sizes, int n_in,
                              void* d_out, int out_size) {
    const float* x     = (const float*)d_in[0];
    const float* w_mu  = (const float*)d_in[1];
    const float* w_rho = (const float*)d_in[2];
    const float* b_mu  = (const float*)d_in[3];
    const float* b_rho = (const float*)d_in[4];
    const float* eps_w = (const float*)d_in[5];
    const float* eps_b = (const float*)d_in[6];
    float* out = (float*)d_out;

    cudaFuncSetAttribute(gemm_kernel, cudaFuncAttributeMaxDynamicSharedMemorySize,
                         SMEM_BYTES);

    prep_x_kernel<<<M_ENS * NBT * NKT, 128>>>(x);          // 8192 CTAs
    prep_w_kernel<<<M_ENS * NOT16 * NKT, 128>>>(w_mu, w_rho, eps_w);  // 4096 CTAs
    int nb = M_ENS * O_DIM;
    prep_b_kernel<<<(nb + 255) / 256, 256>>>(b_mu, b_rho, eps_b, nb);

    gemm_kernel<<<dim3(NOT16, NBT, M_ENS), 128, SMEM_BYTES>>>(out);
}

// round 8
// speedup vs baseline: 7.0103x; 1.0260x over previous
#include <cuda_runtime.h>
#include <cuda_fp16.h>
#include <cstdint>

// ---------------------------------------------------------------------------
// Problem shape
// ---------------------------------------------------------------------------
constexpr int M_ENS = 8, B_DIM = 4096, I_DIM = 2048, O_DIM = 2048;

// GEMM tiling: CTA = 128x128, K-tile 64, 4 warps (2x2), 2 CTAs/SM.
constexpr int CT_M = 128, CT_N = 128, CT_K = 64;
constexpr int NKT = I_DIM / CT_K;    // 32 k-tiles
constexpr int NBT = B_DIM / CT_M;    // 32 row tiles
constexpr int NOT16 = O_DIM / CT_N;  // 16 col tiles
constexpr int IMG_BYTES = CT_M * CT_K * 2;      // 16384 per operand image
constexpr int STAGE_BYTES = 2 * IMG_BYTES;      // 32768
constexpr int STAGES = 3;
constexpr int SMEM_CTRL = 128;                  // mbarriers live here
constexpr int SMEM_BYTES = SMEM_CTRL + STAGES * STAGE_BYTES;  // 98432/CTA

// ---------------------------------------------------------------------------
// Scratch: pre-swizzled smem IMAGES. Image(m,tile,kt) is the exact 16KB the
// gemm wants in shared memory: row r (128B) holds 8 granules; granule slot
// (j ^ rev3(r&7)) stores 8 halves u with k = 32*(j>>2) + 2*(j&3) + (u&1)
// + ((u>>1)&1)*8 + ((u>>2)&1)*16  (mma fragment order).
// ---------------------------------------------------------------------------
__device__ __align__(128) __half g_Xs[(size_t)M_ENS * B_DIM * I_DIM];
__device__ __align__(128) __half g_Ws[(size_t)M_ENS * O_DIM * I_DIM];
__device__ float g_bias[M_ENS * O_DIM];

// ---------------------------------------------------------------------------
// Helpers
// ---------------------------------------------------------------------------
__device__ __forceinline__ float softplus_f(float r) {
    return (r > 15.0f) ? r : log1pf(__expf(r));
}
__device__ __forceinline__ uint32_t smem_u32_of(const void* p) {
    uint32_t a;
    asm("{ .reg .u64 t; cvta.to.shared.u64 t, %1; cvt.u32.u64 %0, t; }"
        : "=r"(a) : "l"(p));
    return a;
}
__device__ __forceinline__ uint32_t rev3(uint32_t x) {
    return ((x & 1u) << 2) | (x & 2u) | ((x >> 2) & 1u);
}
__device__ __forceinline__ void mbar_init(uint32_t mbar, uint32_t cnt) {
    asm volatile("mbarrier.init.shared.b64 [%0], %1;" :: "r"(mbar), "r"(cnt) : "memory");
}
__device__ __forceinline__ void mbar_expect_tx(uint32_t mbar, uint32_t bytes) {
    asm volatile("mbarrier.arrive.expect_tx.shared.b64 _, [%0], %1;"
                 :: "r"(mbar), "r"(bytes) : "memory");
}
__device__ __forceinline__ void mbar_wait(uint32_t mbar, uint32_t parity) {
    asm volatile(
        "{\n\t.reg .pred P;\n\t"
        "W_%=:\n\t"
        "mbarrier.try_wait.parity.acquire.cta.shared::cta.b64 P, [%0], %1, 0x989680;\n\t"
        "@P bra.uni D_%=;\n\t"
        "bra.uni W_%=;\n\t"
        "D_%=:\n\t}"
        :: "r"(mbar), "r"(parity) : "memory");
}
__device__ __forceinline__ void bulk_g2s(uint32_t dst, const void* src,
                                         uint32_t bytes, uint32_t mbar) {
    asm volatile(
        "cp.async.bulk.shared::cluster.global.mbarrier::complete_tx::bytes "
        "[%0], [%1], %2, [%3];"
        :: "r"(dst), "l"(src), "r"(bytes), "r"(mbar) : "memory");
}
__device__ __forceinline__ void mma_f16(float* c, uint32_t a0, uint32_t a1,
                                        uint32_t a2, uint32_t a3,
                                        uint32_t b0, uint32_t b1) {
    asm volatile(
        "mma.sync.aligned.m16n8k16.row.col.f32.f16.f16.f32 "
        "{%0,%1,%2,%3}, {%4,%5,%6,%7}, {%8,%9}, {%0,%1,%2,%3};"
        : "+f"(c[0]), "+f"(c[1]), "+f"(c[2]), "+f"(c[3])
        : "r"(a0), "r"(a1), "r"(a2), "r"(a3), "r"(b0), "r"(b1));
}

// ---------------------------------------------------------------------------
// Prep 1: x -> fp16 smem images. One CTA (128 thr) per (m, bt, kt) image.
// Phase 2 write mapping: 8 consecutive lanes cover the 8 granules of one row
// -> each warp stores 4 x 128B contiguous (coalesced).
// ---------------------------------------------------------------------------
__global__ __launch_bounds__(128)
void prep_x_kernel(const float* __restrict__ x) {
    __shared__ float tile[128][68];
    const int g = blockIdx.x;
    const int kt = g & 31, bt = (g >> 5) & 31, m = g >> 10;
    const int t = threadIdx.x;
    const float* src = x + ((size_t)(m * B_DIM + bt * 128)) * I_DIM + kt * 64;
#pragma unroll
    for (int i = 0; i < 16; i++) {   // 128 rows x 64 floats, coalesced
        int c = t + i * 128;
        int r = c >> 4, q = c & 15;
        float4 v = *reinterpret_cast<const float4*>(src + (size_t)r * I_DIM + q * 4);
        *reinterpret_cast<float4*>(&tile[r][q * 4]) = v;
    }
    __syncthreads();
    char* dst = (char*)g_Xs + ((size_t)((m * NBT + bt) * NKT + kt)) * IMG_BYTES;
#pragma unroll
    for (int i = 0; i < 8; i++) {
        int c = t + i * 128;          // granule-slot id 0..1023
        int r = c >> 3, j = c & 7;    // row, logical granule
        int kb = j >> 2, tt2 = j & 3;
        __half h[8];
#pragma unroll
        for (int u = 0; u < 8; u++) {
            int k = kb * 32 + 2 * tt2 + (u & 1) + ((u >> 1) & 1) * 8 + ((u >> 2) & 1) * 16;
            h[u] = __float2half_rn(tile[r][k]);
        }
        uint32_t off = (uint32_t)r * 128 + ((((uint32_t)j) << 4) ^ (rev3((uint32_t)r & 7) << 4));
        *reinterpret_cast<uint4*>(dst + off) = *reinterpret_cast<uint4*>(h);
    }
}

// ---------------------------------------------------------------------------
// Prep 2: W = mu + softplus(rho)*eps, transpose [I,O]->[O,I], fp16 images.
// One CTA (128 thr) per (m, ot, kt) image. Same coalesced write mapping.
// ---------------------------------------------------------------------------
__global__ __launch_bounds__(128)
void prep_w_kernel(const float* __restrict__ mu, const float* __restrict__ rho,
                   const float* __restrict__ eps) {
    __shared__ float tile[64][132];
    const int g = blockIdx.x;
    const int kt = g & 31, ot = (g >> 5) & 15, m = g >> 9;
    const int t = threadIdx.x;
    const size_t base =
        (size_t)m * I_DIM * O_DIM + (size_t)(kt * 64) * O_DIM + ot * 128;
#pragma unroll
    for (int i = 0; i < 16; i++) {   // 64 rows x 128 floats, coalesced
        int c = t + i * 128;
        int r = c >> 5, q = c & 31;
        size_t idx = base + (size_t)r * O_DIM + q * 4;
        float4 vm = *reinterpret_cast<const float4*>(mu + idx);
        float4 vr = *reinterpret_cast<const float4*>(rho + idx);
        float4 ve = *reinterpret_cast<const float4*>(eps + idx);
        float4 w;
        w.x = fmaf(softplus_f(vr.x), ve.x, vm.x);
        w.y = fmaf(softplus_f(vr.y), ve.y, vm.y);
        w.z = fmaf(softplus_f(vr.z), ve.z, vm.z);
        w.w = fmaf(softplus_f(vr.w), ve.w, vm.w);
        *reinterpret_cast<float4*>(&tile[r][q * 4]) = w;
    }
    __syncthreads();
    char* dst = (char*)g_Ws + ((size_t)((m * NOT16 + ot) * NKT + kt)) * IMG_BYTES;
#pragma unroll
    for (int i = 0; i < 8; i++) {
        int c = t + i * 128;
        int o = c >> 3, j = c & 7;    // output row (O dim), logical granule
        int kb = j >> 2, tt2 = j & 3;
        __half h[8];
#pragma unroll
        for (int u = 0; u < 8; u++) {
            int k = kb * 32 + 2 * tt2 + (u & 1) + ((u >> 1) & 1) * 8 + ((u >> 2) & 1) * 16;
            h[u] = __float2half_rn(tile[k][o]);
        }
        uint32_t off = (uint32_t)o * 128 + ((((uint32_t)j) << 4) ^ (rev3((uint32_t)o & 7) << 4));
        *reinterpret_cast<uint4*>(dst + off) = *reinterpret_cast<uint4*>(h);
    }
}

__global__ void prep_b_kernel(const float* __restrict__ mu,
                              const float* __restrict__ rho,
                              const float* __restrict__ eps, int n) {
    int i = blockIdx.x * blockDim.x + threadIdx.x;
    if (i < n) g_bias[i] = fmaf(softplus_f(rho[i]), eps[i], mu[i]);
}

// ---------------------------------------------------------------------------
// GEMM: fp16 mma.sync.m16n8k16, 4 warps (2x2), warp tile 64x64,
// 3-stage bulk-copy pipeline, main loop unrolled x3 (compile-time stages).
// ---------------------------------------------------------------------------
__global__ __launch_bounds__(128, 2)
void gemm_kernel(float* __restrict__ Out) {
    extern __shared__ __align__(128) uint8_t smem_raw[];
    const uint32_t sb = smem_u32_of(smem_raw);
    const int tid = threadIdx.x, lane = tid & 31, wid = tid >> 5;
    const int gid = lane >> 2, tig = lane & 3;
    const int wm = wid >> 1, wn = wid & 1;
    const int ot = blockIdx.x, bt = blockIdx.y, m = blockIdx.z;

    const char* gA = (const char*)g_Xs + (size_t)((m * NBT + bt) * NKT) * IMG_BYTES;
    const char* gB = (const char*)g_Ws + (size_t)((m * NOT16 + ot) * NKT) * IMG_BYTES;

    if (tid == 0) {
#pragma unroll
        for (int s = 0; s < STAGES; s++) mbar_init(sb + 8 * s, 1);
        asm volatile("fence.proxy.async.shared::cta;" ::: "memory");
    }
    __syncthreads();

    if (tid == 0) {
#pragma unroll
        for (int kt = 0; kt < 2; kt++) {
            uint32_t fb = sb + 8 * kt;
            uint32_t st = sb + SMEM_CTRL + kt * STAGE_BYTES;
            mbar_expect_tx(fb, STAGE_BYTES);
            bulk_g2s(st, gA + (size_t)kt * IMG_BYTES, IMG_BYTES, fb);
            bulk_g2s(st + IMG_BYTES, gB + (size_t)kt * IMG_BYTES, IMG_BYTES, fb);
        }
    }

    float acc[4][8][4];
#pragma unroll
    for (int f = 0; f < 4; f++)
#pragma unroll
        for (int n = 0; n < 8; n++)
#pragma unroll
            for (int q = 0; q < 4; q++) acc[f][n][q] = 0.0f;

    const uint32_t arev = rev3(gid) << 4;
    // loop-invariant row byte offsets within an image
    uint32_t aRow[4], bRow[8];
#pragma unroll
    for (int f = 0; f < 4; f++) aRow[f] = (uint32_t)(wm * 64 + f * 16 + gid) * 128;
#pragma unroll
    for (int n = 0; n < 8; n++) bRow[n] = (uint32_t)(wn * 64 + n * 8 + gid) * 128;

    constexpr int NROUND = (NKT + 2) / 3;  // 11
    for (int rr = 0; rr < NROUND; rr++) {
        const int ph = rr & 1;
#pragma unroll
        for (int ss = 0; ss < 3; ss++) {
            const int kt = rr * 3 + ss;
            if (kt >= NKT) break;
            mbar_wait(sb + 8 * ss, ph);
            __syncthreads();   // all warps done reading the stage we overwrite

            if (tid == 0 && kt + 2 < NKT) {
                const int s2 = (ss + 2 >= 3) ? ss - 1 : ss + 2;  // compile-time
                uint32_t fb = sb + 8 * s2;
                uint32_t st = sb + SMEM_CTRL + s2 * STAGE_BYTES;
                mbar_expect_tx(fb, STAGE_BYTES);
                bulk_g2s(st, gA + (size_t)(kt + 2) * IMG_BYTES, IMG_BYTES, fb);
                bulk_g2s(st + IMG_BYTES, gB + (size_t)(kt + 2) * IMG_BYTES, IMG_BYTES, fb);
            }

            const uint8_t* As = smem_raw + (SMEM_CTRL + ss * STAGE_BYTES);
            const uint8_t* Bs = As + IMG_BYTES;

#pragma unroll
            for (int kb = 0; kb < 2; kb++) {
                const uint32_t gran = (((uint32_t)(kb * 4 + tig)) << 4) ^ arev;
                uint4 aLo[4], aHi[4], bV[8];
#pragma unroll
                for (int n = 0; n < 8; n++)
                    bV[n] = *reinterpret_cast<const uint4*>(Bs + bRow[n] + gran);
#pragma unroll
                for (int f = 0; f < 4; f++) {
                    aLo[f] = *reinterpret_cast<const uint4*>(As + aRow[f] + gran);
                    aHi[f] = *reinterpret_cast<const uint4*>(As + aRow[f] + 8 * 128 + gran);
                }
#pragma unroll
                for (int kg = 0; kg < 2; kg++) {
#pragma unroll
                    for (int f = 0; f < 4; f++) {
                        uint32_t a0 = kg ? aLo[f].z : aLo[f].x;
                        uint32_t a2 = kg ? aLo[f].w : aLo[f].y;
                        uint32_t a1 = kg ? aHi[f].z : aHi[f].x;
                        uint32_t a3 = kg ? aHi[f].w : aHi[f].y;
#pragma unroll
                        for (int n = 0; n < 8; n++) {
                            uint32_t b0 = kg ? bV[n].z : bV[n].x;
                            uint32_t b1 = kg ? bV[n].w : bV[n].y;
                            mma_f16(acc[f][n], a0, a1, a2, a3, b0, b1);
                        }
                    }
                }
            }
        }
    }

    // ---- epilogue: add bias, write out ----
    const float* bias = g_bias + m * O_DIM + ot * CT_N;
    const size_t rowbase = (size_t)m * B_DIM + (size_t)bt * CT_M;
#pragma unroll
    for (int f = 0; f < 4; f++) {
        int r0 = wm * 64 + f * 16 + gid;
#pragma unroll
        for (int n = 0; n < 8; n++) {
            int col = wn * 64 + n * 8 + tig * 2;
            float2 bb = *reinterpret_cast<const float2*>(&bias[col]);
            float2 v0, v1;
            v0.x = acc[f][n][0] + bb.x;
            v0.y = acc[f][n][1] + bb.y;
            v1.x = acc[f][n][2] + bb.x;
            v1.y = acc[f][n][3] + bb.y;
            *reinterpret_cast<float2*>(
                &Out[(rowbase + r0) * O_DIM + (size_t)ot * CT_N + col]) = v0;
            *reinterpret_cast<float2*>(
                &Out[(rowbase + r0 + 8) * O_DIM + (size_t)ot * CT_N + col]) = v1;
        }
    }
}

// ---------------------------------------------------------------------------
// Launch. Inputs: x, weight_mu, weight_rho, bias_mu, bias_rho, eps_w, eps_b
// ---------------------------------------------------------------------------
extern "C" void kernel_launch(void* const* d_in, const int* in_sizes, int n_in,
                              void* d_out, int out_size) {
    const float* x     = (const float*)d_in[0];
    const float* w_mu  = (const float*)d_in[1];
    const float* w_rho = (const float*)d_in[2];
    const float* b_mu  = (const float*)d_in[3];
    const float* b_rho = (const float*)d_in[4];
    const float* eps_w = (const float*)d_in[5];
    const float* eps_b = (const float*)d_in[6];
    float* out = (float*)d_out;

    cudaFuncSetAttribute(gemm_kernel, cudaFuncAttributeMaxDynamicSharedMemorySize,
                         SMEM_BYTES);

    prep_x_kernel<<<M_ENS * NBT * NKT, 128>>>(x);                     // 8192 CTAs
    prep_w_kernel<<<M_ENS * NOT16 * NKT, 128>>>(w_mu, w_rho, eps_w);  // 4096 CTAs
    int nb = M_ENS * O_DIM;
    prep_b_kernel<<<(nb + 255) / 256, 256>>>(b_mu, b_rho, eps_b, nb);

    gemm_kernel<<<dim3(NOT16, NBT, M_ENS), 128, SMEM_BYTES>>>(out);
}

// round 9
// speedup vs baseline: 7.1342x; 1.0177x over previous
#include <cuda_runtime.h>
#include <cuda_fp16.h>
#include <cstdint>

// ---------------------------------------------------------------------------
// Problem shape
// ---------------------------------------------------------------------------
constexpr int M_ENS = 8, B_DIM = 4096, I_DIM = 2048, O_DIM = 2048;

// GEMM tiling: CTA = 128x128, K-tile 64, 4 warps (2x2), 2 CTAs/SM.
constexpr int CT_M = 128, CT_N = 128, CT_K = 64;
constexpr int NKT = I_DIM / CT_K;    // 32 k-tiles
constexpr int NBT = B_DIM / CT_M;    // 32 row tiles
constexpr int NOT16 = O_DIM / CT_N;  // 16 col tiles
constexpr int IMG_BYTES = CT_M * CT_K * 2;      // 16384 per operand image
constexpr int STAGE_BYTES = 2 * IMG_BYTES;      // 32768
constexpr int STAGES = 3;
constexpr int SMEM_CTRL = 128;                  // mbarriers live here
constexpr int SMEM_BYTES = SMEM_CTRL + STAGES * STAGE_BYTES;  // 98432/CTA

// ---------------------------------------------------------------------------
// Scratch: pre-swizzled smem IMAGES (see round-7/8 layout comment).
// ---------------------------------------------------------------------------
__device__ __align__(128) __half g_Xs[(size_t)M_ENS * B_DIM * I_DIM];
__device__ __align__(128) __half g_Ws[(size_t)M_ENS * O_DIM * I_DIM];
__device__ float g_bias[M_ENS * O_DIM];

// ---------------------------------------------------------------------------
// Helpers
// ---------------------------------------------------------------------------
__device__ __forceinline__ float softplus_f(float r) {
    return (r > 15.0f) ? r : log1pf(__expf(r));
}
__device__ __forceinline__ uint32_t smem_u32_of(const void* p) {
    uint32_t a;
    asm("{ .reg .u64 t; cvta.to.shared.u64 t, %1; cvt.u32.u64 %0, t; }"
        : "=r"(a) : "l"(p));
    return a;
}
__device__ __forceinline__ uint32_t rev3(uint32_t x) {
    return ((x & 1u) << 2) | (x & 2u) | ((x >> 2) & 1u);
}
__device__ __forceinline__ void mbar_init(uint32_t mbar, uint32_t cnt) {
    asm volatile("mbarrier.init.shared.b64 [%0], %1;" :: "r"(mbar), "r"(cnt) : "memory");
}
__device__ __forceinline__ void mbar_expect_tx(uint32_t mbar, uint32_t bytes) {
    asm volatile("mbarrier.arrive.expect_tx.shared.b64 _, [%0], %1;"
                 :: "r"(mbar), "r"(bytes) : "memory");
}
__device__ __forceinline__ void mbar_arrive(uint32_t mbar) {
    asm volatile("mbarrier.arrive.shared.b64 _, [%0];" :: "r"(mbar) : "memory");
}
__device__ __forceinline__ void mbar_wait(uint32_t mbar, uint32_t parity) {
    asm volatile(
        "{\n\t.reg .pred P;\n\t"
        "W_%=:\n\t"
        "mbarrier.try_wait.parity.acquire.cta.shared::cta.b64 P, [%0], %1, 0x989680;\n\t"
        "@P bra.uni D_%=;\n\t"
        "bra.uni W_%=;\n\t"
        "D_%=:\n\t}"
        :: "r"(mbar), "r"(parity) : "memory");
}
__device__ __forceinline__ void bulk_g2s(uint32_t dst, const void* src,
                                         uint32_t bytes, uint32_t mbar) {
    asm volatile(
        "cp.async.bulk.shared::cluster.global.mbarrier::complete_tx::bytes "
        "[%0], [%1], %2, [%3];"
        :: "r"(dst), "l"(src), "r"(bytes), "r"(mbar) : "memory");
}
__device__ __forceinline__ void mma_f16(float* c, uint32_t a0, uint32_t a1,
                                        uint32_t a2, uint32_t a3,
                                        uint32_t b0, uint32_t b1) {
    asm volatile(
        "mma.sync.aligned.m16n8k16.row.col.f32.f16.f16.f32 "
        "{%0,%1,%2,%3}, {%4,%5,%6,%7}, {%8,%9}, {%0,%1,%2,%3};"
        : "+f"(c[0]), "+f"(c[1]), "+f"(c[2]), "+f"(c[3])
        : "r"(a0), "r"(a1), "r"(a2), "r"(a3), "r"(b0), "r"(b1));
}

// ---------------------------------------------------------------------------
// Prep 1: x -> fp16 smem images. One CTA (128 thr) per (m, bt, kt) image.
// ---------------------------------------------------------------------------
__global__ __launch_bounds__(128)
void prep_x_kernel(const float* __restrict__ x) {
    __shared__ float tile[128][68];
    const int g = blockIdx.x;
    const int kt = g & 31, bt = (g >> 5) & 31, m = g >> 10;
    const int t = threadIdx.x;
    const float* src = x + ((size_t)(m * B_DIM + bt * 128)) * I_DIM + kt * 64;
#pragma unroll
    for (int i = 0; i < 16; i++) {
        int c = t + i * 128;
        int r = c >> 4, q = c & 15;
        float4 v = *reinterpret_cast<const float4*>(src + (size_t)r * I_DIM + q * 4);
        *reinterpret_cast<float4*>(&tile[r][q * 4]) = v;
    }
    __syncthreads();
    char* dst = (char*)g_Xs + ((size_t)((m * NBT + bt) * NKT + kt)) * IMG_BYTES;
#pragma unroll
    for (int i = 0; i < 8; i++) {
        int c = t + i * 128;
        int r = c >> 3, j = c & 7;
        int kb = j >> 2, tt2 = j & 3;
        __half h[8];
#pragma unroll
        for (int u = 0; u < 8; u++) {
            int k = kb * 32 + 2 * tt2 + (u & 1) + ((u >> 1) & 1) * 8 + ((u >> 2) & 1) * 16;
            h[u] = __float2half_rn(tile[r][k]);
        }
        uint32_t off = (uint32_t)r * 128 + ((((uint32_t)j) << 4) ^ (rev3((uint32_t)r & 7) << 4));
        *reinterpret_cast<uint4*>(dst + off) = *reinterpret_cast<uint4*>(h);
    }
}

// ---------------------------------------------------------------------------
// Prep 2: W = mu + softplus(rho)*eps, transpose, fp16 images.
// ---------------------------------------------------------------------------
__global__ __launch_bounds__(128)
void prep_w_kernel(const float* __restrict__ mu, const float* __restrict__ rho,
                   const float* __restrict__ eps) {
    __shared__ float tile[64][132];
    const int g = blockIdx.x;
    const int kt = g & 31, ot = (g >> 5) & 15, m = g >> 9;
    const int t = threadIdx.x;
    const size_t base =
        (size_t)m * I_DIM * O_DIM + (size_t)(kt * 64) * O_DIM + ot * 128;
#pragma unroll
    for (int i = 0; i < 16; i++) {
        int c = t + i * 128;
        int r = c >> 5, q = c & 31;
        size_t idx = base + (size_t)r * O_DIM + q * 4;
        float4 vm = *reinterpret_cast<const float4*>(mu + idx);
        float4 vr = *reinterpret_cast<const float4*>(rho + idx);
        float4 ve = *reinterpret_cast<const float4*>(eps + idx);
        float4 w;
        w.x = fmaf(softplus_f(vr.x), ve.x, vm.x);
        w.y = fmaf(softplus_f(vr.y), ve.y, vm.y);
        w.z = fmaf(softplus_f(vr.z), ve.z, vm.z);
        w.w = fmaf(softplus_f(vr.w), ve.w, vm.w);
        *reinterpret_cast<float4*>(&tile[r][q * 4]) = w;
    }
    __syncthreads();
    char* dst = (char*)g_Ws + ((size_t)((m * NOT16 + ot) * NKT + kt)) * IMG_BYTES;
#pragma unroll
    for (int i = 0; i < 8; i++) {
        int c = t + i * 128;
        int o = c >> 3, j = c & 7;
        int kb = j >> 2, tt2 = j & 3;
        __half h[8];
#pragma unroll
        for (int u = 0; u < 8; u++) {
            int k = kb * 32 + 2 * tt2 + (u & 1) + ((u >> 1) & 1) * 8 + ((u >> 2) & 1) * 16;
            h[u] = __float2half_rn(tile[k][o]);
        }
        uint32_t off = (uint32_t)o * 128 + ((((uint32_t)j) << 4) ^ (rev3((uint32_t)o & 7) << 4));
        *reinterpret_cast<uint4*>(dst + off) = *reinterpret_cast<uint4*>(h);
    }
}

__global__ void prep_b_kernel(const float* __restrict__ mu,
                              const float* __restrict__ rho,
                              const float* __restrict__ eps, int n) {
    int i = blockIdx.x * blockDim.x + threadIdx.x;
    if (i < n) g_bias[i] = fmaf(softplus_f(rho[i]), eps[i], mu[i]);
}

// ---------------------------------------------------------------------------
// GEMM: fp16 mma.sync.m16n8k16, 4 warps (2x2), warp tile 64x64, 3-stage
// bulk-copy pipeline with full/empty mbarriers — NO per-tile __syncthreads.
//   full[s]  : tx-based, producer-issued bulk copies
//   empty[s] : count=4, lane0 of each warp arrives after its MMAs issue
// Only warp 0 (tid 0) ever blocks on empty[]; warps drift and overlap.
// ---------------------------------------------------------------------------
__global__ __launch_bounds__(128, 2)
void gemm_kernel(float* __restrict__ Out) {
    extern __shared__ __align__(128) uint8_t smem_raw[];
    const uint32_t sb = smem_u32_of(smem_raw);
    const int tid = threadIdx.x, lane = tid & 31, wid = tid >> 5;
    const int gid = lane >> 2, tig = lane & 3;
    const int wm = wid >> 1, wn = wid & 1;
    const int ot = blockIdx.x, bt = blockIdx.y, m = blockIdx.z;

    const char* gA = (const char*)g_Xs + (size_t)((m * NBT + bt) * NKT) * IMG_BYTES;
    const char* gB = (const char*)g_Ws + (size_t)((m * NOT16 + ot) * NKT) * IMG_BYTES;

    // mbarrier layout: full[s] @ sb+8s, empty[s] @ sb+24+8s
    if (tid == 0) {
#pragma unroll
        for (int s = 0; s < STAGES; s++) {
            mbar_init(sb + 8 * s, 1);
            mbar_init(sb + 24 + 8 * s, 4);
        }
        asm volatile("fence.proxy.async.shared::cta;" ::: "memory");
    }
    __syncthreads();

    if (tid == 0) {
#pragma unroll
        for (int kt = 0; kt < 2; kt++) {
            uint32_t fb = sb + 8 * kt;
            uint32_t st = sb + SMEM_CTRL + kt * STAGE_BYTES;
            mbar_expect_tx(fb, STAGE_BYTES);
            bulk_g2s(st, gA + (size_t)kt * IMG_BYTES, IMG_BYTES, fb);
            bulk_g2s(st + IMG_BYTES, gB + (size_t)kt * IMG_BYTES, IMG_BYTES, fb);
        }
    }

    float acc[4][8][4];
#pragma unroll
    for (int f = 0; f < 4; f++)
#pragma unroll
        for (int n = 0; n < 8; n++)
#pragma unroll
            for (int q = 0; q < 4; q++) acc[f][n][q] = 0.0f;

    const uint32_t arev = rev3(gid) << 4;
    uint32_t aRow[4], bRow[8];
#pragma unroll
    for (int f = 0; f < 4; f++) aRow[f] = (uint32_t)(wm * 64 + f * 16 + gid) * 128;
#pragma unroll
    for (int n = 0; n < 8; n++) bRow[n] = (uint32_t)(wn * 64 + n * 8 + gid) * 128;

    constexpr int NROUND = (NKT + 2) / 3;  // 11
    for (int rr = 0; rr < NROUND; rr++) {
        const int phf = rr & 1;
#pragma unroll
        for (int ss = 0; ss < 3; ss++) {
            const int kt = rr * 3 + ss;
            if (kt >= NKT) break;
            mbar_wait(sb + 8 * ss, phf);   // stage ss full for round rr

            // producer: refill stage s2 = (ss+2)%3 with tile kt+2
            if (tid == 0 && kt + 2 < NKT) {
                const int s2 = (ss + 2 >= 3) ? ss - 1 : ss + 2;  // compile-time
                if (kt >= 1) {
                    // wait until all warps finished the stage's previous tile
                    const int phe = (ss == 0) ? ((rr - 1) & 1) : (rr & 1);
                    mbar_wait(sb + 24 + 8 * s2, phe);
                }
                uint32_t fb = sb + 8 * s2;
                uint32_t st = sb + SMEM_CTRL + s2 * STAGE_BYTES;
                mbar_expect_tx(fb, STAGE_BYTES);
                bulk_g2s(st, gA + (size_t)(kt + 2) * IMG_BYTES, IMG_BYTES, fb);
                bulk_g2s(st + IMG_BYTES, gB + (size_t)(kt + 2) * IMG_BYTES, IMG_BYTES, fb);
            }

            const uint8_t* As = smem_raw + (SMEM_CTRL + ss * STAGE_BYTES);
            const uint8_t* Bs = As + IMG_BYTES;

#pragma unroll
            for (int kb = 0; kb < 2; kb++) {
                const uint32_t gran = (((uint32_t)(kb * 4 + tig)) << 4) ^ arev;
                uint4 aLo[4], aHi[4], bV[8];
#pragma unroll
                for (int n = 0; n < 8; n++)
                    bV[n] = *reinterpret_cast<const uint4*>(Bs + bRow[n] + gran);
#pragma unroll
                for (int f = 0; f < 4; f++) {
                    aLo[f] = *reinterpret_cast<const uint4*>(As + aRow[f] + gran);
                    aHi[f] = *reinterpret_cast<const uint4*>(As + aRow[f] + 8 * 128 + gran);
                }
#pragma unroll
                for (int kg = 0; kg < 2; kg++) {
#pragma unroll
                    for (int f = 0; f < 4; f++) {
                        uint32_t a0 = kg ? aLo[f].z : aLo[f].x;
                        uint32_t a2 = kg ? aLo[f].w : aLo[f].y;
                        uint32_t a1 = kg ? aHi[f].z : aHi[f].x;
                        uint32_t a3 = kg ? aHi[f].w : aHi[f].y;
#pragma unroll
                        for (int n = 0; n < 8; n++) {
                            uint32_t b0 = kg ? bV[n].z : bV[n].x;
                            uint32_t b1 = kg ? bV[n].w : bV[n].y;
                            mma_f16(acc[f][n], a0, a1, a2, a3, b0, b1);
                        }
                    }
                }
            }
            // MMAs for stage ss issued -> registers hold the data; stage is dead
            // for this warp. One arrive per warp (count=4).
            if (lane == 0) mbar_arrive(sb + 24 + 8 * ss);
        }
    }

    // ---- epilogue: add bias, write out ----
    const float* bias = g_bias + m * O_DIM + ot * CT_N;
    const size_t rowbase = (size_t)m * B_DIM + (size_t)bt * CT_M;
#pragma unroll
    for (int f = 0; f < 4; f++) {
        int r0 = wm * 64 + f * 16 + gid;
#pragma unroll
        for (int n = 0; n < 8; n++) {
            int col = wn * 64 + n * 8 + tig * 2;
            float2 bb = *reinterpret_cast<const float2*>(&bias[col]);
            float2 v0, v1;
            v0.x = acc[f][n][0] + bb.x;
            v0.y = acc[f][n][1] + bb.y;
            v1.x = acc[f][n][2] + bb.x;
            v1.y = acc[f][n][3] + bb.y;
            *reinterpret_cast<float2*>(
                &Out[(rowbase + r0) * O_DIM + (size_t)ot * CT_N + col]) = v0;
            *reinterpret_cast<float2*>(
                &Out[(rowbase + r0 + 8) * O_DIM + (size_t)ot * CT_N + col]) = v1;
        }
    }
}

// ---------------------------------------------------------------------------
// Launch. Inputs: x, weight_mu, weight_rho, bias_mu, bias_rho, eps_w, eps_b
// ---------------------------------------------------------------------------
extern "C" void kernel_launch(void* const* d_in, const int* in_sizes, int n_in,
                              void* d_out, int out_size) {
    const float* x     = (const float*)d_in[0];
    const float* w_mu  = (const float*)d_in[1];
    const float* w_rho = (const float*)d_in[2];
    const float* b_mu  = (const float*)d_in[3];
    const float* b_rho = (const float*)d_in[4];
    const float* eps_w = (const float*)d_in[5];
    const float* eps_b = (const float*)d_in[6];
    float* out = (float*)d_out;

    cudaFuncSetAttribute(gemm_kernel, cudaFuncAttributeMaxDynamicSharedMemorySize,
                         SMEM_BYTES);

    prep_x_kernel<<<M_ENS * NBT * NKT, 128>>>(x);                     // 8192 CTAs
    prep_w_kernel<<<M_ENS * NOT16 * NKT, 128>>>(w_mu, w_rho, eps_w);  // 4096 CTAs
    int nb = M_ENS * O_DIM;
    prep_b_kernel<<<(nb + 255) / 256, 256>>>(b_mu, b_rho, eps_b, nb);

    gemm_kernel<<<dim3(NOT16, NBT, M_ENS), 128, SMEM_BYTES>>>(out);
}